// round 12
// baseline (speedup 1.0000x reference)
#include <cuda_runtime.h>

// RouterModel: N=32768 tokens, D=1024, P=2 paths.
// d = x . (W[:,0]-W[:,1]); path = d>=0 ? 0 : 1; gate = sigmoid(|d|)
// out = [x0 | x1 | xc], each [N, D] float32.
//
// 64 threads (2 warps) per token, v8 (256-bit) global accesses, ILP=2:
// thread t owns floats {8t..8t+7} and {8t+512..8t+519}. Two front-batched
// LDG.E.256, then the shortest possible reduction chain: warp shfl + a
// 2-value smem exchange (2-warp barrier), then 6 STG.E.256.

#define N_TOK   32768
#define DHID    1024
#define THREADS 64
#define HALF    (DHID / 2)   // 512 floats

__global__ __launch_bounds__(THREADS, 24) void router_kernel(
    const float* __restrict__ x, const float* __restrict__ W,
    float* __restrict__ out)
{
    const int n = blockIdx.x;
    const int t = threadIdx.x;

    // Two front-batched 256-bit loads of this thread's row slices.
    const float* xr = x + (size_t)n * DHID;
    float a0,a1,a2,a3,a4,a5,a6,a7;
    float b0,b1,b2,b3,b4,b5,b6,b7;
    asm volatile("ld.global.v8.f32 {%0,%1,%2,%3,%4,%5,%6,%7}, [%8];"
                 : "=f"(a0),"=f"(a1),"=f"(a2),"=f"(a3),
                   "=f"(a4),"=f"(a5),"=f"(a6),"=f"(a7)
                 : "l"(xr + 8 * t));
    asm volatile("ld.global.v8.f32 {%0,%1,%2,%3,%4,%5,%6,%7}, [%8];"
                 : "=f"(b0),"=f"(b1),"=f"(b2),"=f"(b3),
                   "=f"(b4),"=f"(b5),"=f"(b6),"=f"(b7)
                 : "l"(xr + HALF + 8 * t));

    // W layout [D,2] row-major: (W0,W1) pairs interleaved; float4 k holds
    // rows 2k,2k+1. Slice A rows 8t..8t+7 -> float4 4t..4t+3; slice B +256.
    const float4* w4 = reinterpret_cast<const float4*>(W);
    const float4 wa0 = __ldg(w4 + 4 * t);
    const float4 wa1 = __ldg(w4 + 4 * t + 1);
    const float4 wa2 = __ldg(w4 + 4 * t + 2);
    const float4 wa3 = __ldg(w4 + 4 * t + 3);
    const float4 wb0 = __ldg(w4 + 4 * t + 256);
    const float4 wb1 = __ldg(w4 + 4 * t + 257);
    const float4 wb2 = __ldg(w4 + 4 * t + 258);
    const float4 wb3 = __ldg(w4 + 4 * t + 259);

    float p = a0 * (wa0.x - wa0.y) + a1 * (wa0.z - wa0.w)
            + a2 * (wa1.x - wa1.y) + a3 * (wa1.z - wa1.w)
            + a4 * (wa2.x - wa2.y) + a5 * (wa2.z - wa2.w)
            + a6 * (wa3.x - wa3.y) + a7 * (wa3.z - wa3.w)
            + b0 * (wb0.x - wb0.y) + b1 * (wb0.z - wb0.w)
            + b2 * (wb1.x - wb1.y) + b3 * (wb1.z - wb1.w)
            + b4 * (wb2.x - wb2.y) + b5 * (wb2.z - wb2.w)
            + b6 * (wb3.x - wb3.y) + b7 * (wb3.z - wb3.w);

    // Warp reduce, then a 2-value smem exchange (only 2 warps in the CTA).
    #pragma unroll
    for (int o = 16; o > 0; o >>= 1)
        p += __shfl_xor_sync(0xffffffffu, p, o);

    __shared__ float s[2];
    const int wid = t >> 5, lid = t & 31;
    if (lid == 0) s[wid] = p;
    __syncthreads();                       // 2-warp barrier: minimal skew
    const float d = s[0] + s[1];

    // gate = softmax max-prob = sigmoid(|d|); path 0 iff d >= 0 (argmax tie -> 0)
    const float g = 1.0f / (1.0f + __expf(-fabsf(d)));
    const float g0 = (d >= 0.0f) ? g : 0.0f;   // x0 gate
    const float g1 = (d >= 0.0f) ? 0.0f : g;   // x1 gate

    const size_t sect = (size_t)N_TOK * DHID;
    float* oa = out + (size_t)n * DHID + 8 * t;   // slice A base (x0 section)
    float* ob = oa + HALF;                         // slice B base (x0 section)

    #define ST8(ptr, s0) \
        asm volatile("st.global.v8.f32 [%0], {%1,%2,%3,%4,%5,%6,%7,%8};" \
            :: "l"(ptr), \
               "f"(a0*(s0)), "f"(a1*(s0)), "f"(a2*(s0)), "f"(a3*(s0)), \
               "f"(a4*(s0)), "f"(a5*(s0)), "f"(a6*(s0)), "f"(a7*(s0)) : "memory")
    #define ST8B(ptr, s0) \
        asm volatile("st.global.v8.f32 [%0], {%1,%2,%3,%4,%5,%6,%7,%8};" \
            :: "l"(ptr), \
               "f"(b0*(s0)), "f"(b1*(s0)), "f"(b2*(s0)), "f"(b3*(s0)), \
               "f"(b4*(s0)), "f"(b5*(s0)), "f"(b6*(s0)), "f"(b7*(s0)) : "memory")

    ST8 (oa,            g0);   // x0 slice A
    ST8B(ob,            g0);   // x0 slice B
    ST8 (oa + sect,     g1);   // x1 slice A
    ST8B(ob + sect,     g1);   // x1 slice B
    ST8 (oa + 2 * sect, g);    // xc slice A
    ST8B(ob + 2 * sect, g);    // xc slice B

    #undef ST8
    #undef ST8B
}

extern "C" void kernel_launch(void* const* d_in, const int* in_sizes, int n_in,
                              void* d_out, int out_size) {
    const float* x = (const float*)d_in[0];   // [N, D] float32
    const float* W = (const float*)d_in[1];   // [D, 2] float32
    float* out = (float*)d_out;               // [3, N, D] float32

    router_kernel<<<N_TOK, THREADS>>>(x, W, out);
}

// round 13
// speedup vs baseline: 1.0076x; 1.0076x over previous
#include <cuda_runtime.h>

// RouterModel: N=32768 tokens, D=1024, P=2 paths.
// d = x . (W[:,0]-W[:,1]); path = d>=0 ? 0 : 1; gate = sigmoid(|d|)
// out = [x0 | x1 | xc], each [N, D] float32.
//
// Block-per-token, 256 threads (measured-best structure), single launch.
// Per thread: 1x LDG.128 of x (streaming) + 1x LDG.256 of W (32 contiguous
// bytes = rows 8t..8t+7, L1-hit after wave 1), folded to wdiff in registers.
// Minimal L1tex wavefronts per token: 2 loads + 3 stores per thread.

#define N_TOK   32768
#define DHID    1024
#define THREADS 256   // DHID/4 float4 lanes per row

__global__ __launch_bounds__(THREADS) void router_kernel(
    const float* __restrict__ x, const float* __restrict__ W,
    float* __restrict__ out)
{
    const int n = blockIdx.x;
    const int t = threadIdx.x;

    // Streaming 128-bit load of this thread's float4 slice of the token row.
    const float4 v = __ldcs(reinterpret_cast<const float4*>(x + (size_t)n * DHID) + t);

    // One 256-bit load of W floats 8t..8t+7 (layout [D,2]: (W0,W1) pairs).
    // 32B-aligned since W is allocation-aligned. L1-hit after wave 1.
    float w0,w1,w2,w3,w4,w5,w6,w7;
    asm("ld.global.nc.v8.f32 {%0,%1,%2,%3,%4,%5,%6,%7}, [%8];"
        : "=f"(w0),"=f"(w1),"=f"(w2),"=f"(w3),
          "=f"(w4),"=f"(w5),"=f"(w6),"=f"(w7)
        : "l"(W + 8 * t));

    // Partial dot with (W0 - W1), folded in registers.
    float p = v.x * (w0 - w1) + v.y * (w2 - w3)
            + v.z * (w4 - w5) + v.w * (w6 - w7);

    // Warp reduce.
    #pragma unroll
    for (int o = 16; o > 0; o >>= 1)
        p += __shfl_xor_sync(0xffffffffu, p, o);

    __shared__ float s[THREADS / 32];
    const int wid = t >> 5, lid = t & 31;
    if (lid == 0) s[wid] = p;
    __syncthreads();

    float d = 0.0f;
    #pragma unroll
    for (int i = 0; i < THREADS / 32; i++) d += s[i];   // broadcast, conflict-free

    // gate = softmax max-prob = sigmoid(|d|); path 0 iff d >= 0 (argmax tie -> 0)
    const float g = 1.0f / (1.0f + __expf(-fabsf(d)));
    const bool  path0 = (d >= 0.0f);

    const float4 sv   = make_float4(v.x * g, v.y * g, v.z * g, v.w * g);
    const float4 zero = make_float4(0.f, 0.f, 0.f, 0.f);

    const size_t row4  = (size_t)n * (DHID / 4) + t;   // float4 index
    const size_t sect4 = (size_t)N_TOK * (DHID / 4);
    float4* o = reinterpret_cast<float4*>(out);

    // Streaming 128-bit stores (write-once outputs).
    __stcs(o + row4,             path0 ? sv   : zero);  // x0
    __stcs(o + sect4 + row4,     path0 ? zero : sv);    // x1
    __stcs(o + 2 * sect4 + row4, sv);                   // xc
}

extern "C" void kernel_launch(void* const* d_in, const int* in_sizes, int n_in,
                              void* d_out, int out_size) {
    const float* x = (const float*)d_in[0];   // [N, D] float32
    const float* W = (const float*)d_in[1];   // [D, 2] float32
    float* out = (float*)d_out;               // [3, N, D] float32

    router_kernel<<<N_TOK, THREADS>>>(x, W, out);
}

// round 14
// speedup vs baseline: 1.0088x; 1.0011x over previous
#include <cuda_runtime.h>

// RouterModel: N=32768 tokens, D=1024, P=2 paths.
// d = x . (W[:,0]-W[:,1]); path = d>=0 ? 0 : 1; gate = sigmoid(|d|)
// out = [x0 | x1 | xc], each [N, D] float32.
//
// FINAL (measured-best total config, R4): single fused launch,
// block-per-token, 256 threads x 1 float4, streaming cache ops.
// Campaign conclusion: kernel is at the HBM roofline for a 1-read:3-write
// stream (~6.07 TB/s achieved, 536.9 MB mandatory traffic -> ~79 us floor);
// nine structural variants bracket 78.5-83 us kernel, none move DRAM%.

#define N_TOK   32768
#define DHID    1024
#define THREADS 256   // DHID/4 float4 lanes per row

__global__ __launch_bounds__(THREADS) void router_kernel(
    const float* __restrict__ x, const float* __restrict__ W,
    float* __restrict__ out)
{
    const int n = blockIdx.x;
    const int t = threadIdx.x;

    // Streaming load of this thread's float4 slice of the token row (no reuse).
    const float4 v = __ldcs(reinterpret_cast<const float4*>(x + (size_t)n * DHID) + t);

    // W rows 4t..4t+3, layout [D,2] row-major: (W0,W1) pairs interleaved.
    // 2x LDG.128, L1-hit after wave 1.
    const float4 wa = __ldg(reinterpret_cast<const float4*>(W) + 2 * t);
    const float4 wb = __ldg(reinterpret_cast<const float4*>(W) + 2 * t + 1);

    // Partial dot with (W0 - W1), folded in registers.
    float p = v.x * (wa.x - wa.y) + v.y * (wa.z - wa.w)
            + v.z * (wb.x - wb.y) + v.w * (wb.z - wb.w);

    // Warp reduce.
    #pragma unroll
    for (int o = 16; o > 0; o >>= 1)
        p += __shfl_xor_sync(0xffffffffu, p, o);

    __shared__ float s[THREADS / 32];
    const int wid = t >> 5, lid = t & 31;
    if (lid == 0) s[wid] = p;
    __syncthreads();

    float d = 0.0f;
    #pragma unroll
    for (int i = 0; i < THREADS / 32; i++) d += s[i];   // broadcast, conflict-free

    // gate = softmax max-prob = sigmoid(|d|); path 0 iff d >= 0 (argmax tie -> 0)
    const float g = 1.0f / (1.0f + __expf(-fabsf(d)));
    const bool  path0 = (d >= 0.0f);

    const float4 sv   = make_float4(v.x * g, v.y * g, v.z * g, v.w * g);
    const float4 zero = make_float4(0.f, 0.f, 0.f, 0.f);

    const size_t row4  = (size_t)n * (DHID / 4) + t;   // float4 index
    const size_t sect4 = (size_t)N_TOK * (DHID / 4);
    float4* o = reinterpret_cast<float4*>(out);

    // Streaming stores: outputs are write-once.
    __stcs(o + row4,             path0 ? sv   : zero);  // x0
    __stcs(o + sect4 + row4,     path0 ? zero : sv);    // x1
    __stcs(o + 2 * sect4 + row4, sv);                   // xc
}

extern "C" void kernel_launch(void* const* d_in, const int* in_sizes, int n_in,
                              void* d_out, int out_size) {
    const float* x = (const float*)d_in[0];   // [N, D] float32
    const float* W = (const float*)d_in[1];   // [D, 2] float32
    float* out = (float*)d_out;               // [3, N, D] float32

    router_kernel<<<N_TOK, THREADS>>>(x, W, out);
}

// round 15
// speedup vs baseline: 1.0091x; 1.0004x over previous
#include <cuda_runtime.h>

// RouterModel: N=32768 tokens, D=1024, P=2 paths.
// d = x . (W[:,0]-W[:,1]); path = d>=0 ? 0 : 1; gate = sigmoid(|d|)
// out = [x0 | x1 | xc], each [N, D] float32.
//
// Best-measured config (R4 family): single launch, block-per-token,
// 256 threads x 1 float4, streaming cache ops. Epilogue tweak: partials
// summed via two LDS.128 instead of eight LDS.32.
// Kernel is at the HBM roofline (~6.07 TB/s achieved on 537 MB mandatory
// traffic -> ~79 us floor); all structural variants are noise around it.

#define N_TOK   32768
#define DHID    1024
#define THREADS 256   // DHID/4 float4 lanes per row

__global__ __launch_bounds__(THREADS) void router_kernel(
    const float* __restrict__ x, const float* __restrict__ W,
    float* __restrict__ out)
{
    const int n = blockIdx.x;
    const int t = threadIdx.x;

    // Streaming load of this thread's float4 slice of the token row (no reuse).
    const float4 v = __ldcs(reinterpret_cast<const float4*>(x + (size_t)n * DHID) + t);

    // W rows 4t..4t+3, layout [D,2] row-major: (W0,W1) pairs interleaved.
    // 2x LDG.128, L1-hit after wave 1.
    const float4 wa = __ldg(reinterpret_cast<const float4*>(W) + 2 * t);
    const float4 wb = __ldg(reinterpret_cast<const float4*>(W) + 2 * t + 1);

    // Partial dot with (W0 - W1), folded in registers.
    float p = v.x * (wa.x - wa.y) + v.y * (wa.z - wa.w)
            + v.z * (wb.x - wb.y) + v.w * (wb.z - wb.w);

    // Warp reduce.
    #pragma unroll
    for (int o = 16; o > 0; o >>= 1)
        p += __shfl_xor_sync(0xffffffffu, p, o);

    __shared__ __align__(32) float s[THREADS / 32];
    const int wid = t >> 5, lid = t & 31;
    if (lid == 0) s[wid] = p;
    __syncthreads();

    // Sum 8 partials as two float4 (2x LDS.128, broadcast, conflict-free).
    const float4 s0 = reinterpret_cast<const float4*>(s)[0];
    const float4 s1 = reinterpret_cast<const float4*>(s)[1];
    const float d = (s0.x + s0.y) + (s0.z + s0.w)
                  + (s1.x + s1.y) + (s1.z + s1.w);

    // gate = softmax max-prob = sigmoid(|d|); path 0 iff d >= 0 (argmax tie -> 0)
    const float g = 1.0f / (1.0f + __expf(-fabsf(d)));
    const bool  path0 = (d >= 0.0f);

    const float4 sv   = make_float4(v.x * g, v.y * g, v.z * g, v.w * g);
    const float4 zero = make_float4(0.f, 0.f, 0.f, 0.f);

    const size_t row4  = (size_t)n * (DHID / 4) + t;   // float4 index
    const size_t sect4 = (size_t)N_TOK * (DHID / 4);
    float4* o = reinterpret_cast<float4*>(out);

    // Streaming stores: outputs are write-once.
    __stcs(o + row4,             path0 ? sv   : zero);  // x0
    __stcs(o + sect4 + row4,     path0 ? zero : sv);    // x1
    __stcs(o + 2 * sect4 + row4, sv);                   // xc
}

extern "C" void kernel_launch(void* const* d_in, const int* in_sizes, int n_in,
                              void* d_out, int out_size) {
    const float* x = (const float*)d_in[0];   // [N, D] float32
    const float* W = (const float*)d_in[1];   // [D, 2] float32
    float* out = (float*)d_out;               // [3, N, D] float32

    router_kernel<<<N_TOK, THREADS>>>(x, W, out);
}